// round 6
// baseline (speedup 1.0000x reference)
#include <cuda_runtime.h>
#include <cuda_bf16.h>

#define NN   100000
#define EE   1600000
#define EOUT 400000
#define HIDD 64
#define GB   ((NN + 255) / 256)          // 391 gemm/apply blocks
#define SCAN_BLOCKS  ((NN + 1023) / 1024)
#define BN_EPS 1e-5f

// ---------------- scratch (device globals; no allocation) ----------------
__device__ float g_dinv[NN];
__device__ int   g_deg[NN];
__device__ int   g_rowptr[NN + 1];
__device__ int   g_cursor[NN];
__device__ int   g_bsum[SCAN_BLOCKS];
__device__ int   g_boff[SCAN_BLOCKS];
__device__ int2  g_csr[EE];          // (src, norm-bits)
__device__ float g_x  [NN * HIDD];   // x_embed
__device__ float g_hw [NN * HIDD];   // aggregated x (pre-GEMM)
__device__ float g_agg[NN * HIDD];   // conv output
__device__ float g_part[GB * 128];   // per-gemm-block partial sum/sumsq
__device__ float g_scale[HIDD];
__device__ float g_shift[HIDD];
__device__ unsigned g_ticket;        // zero-init; last block resets
__device__ float4 g_head[NN];        // (a0,a1,b0,b1) edge-head halves

// ---------------- degree ----------------
__global__ void k_deg_init() {
    int i = blockIdx.x * 256 + threadIdx.x;
    if (i < NN) g_deg[i] = 1;            // self loop
}

__global__ void k_deg_count(const int* __restrict__ ei) {
    int e = blockIdx.x * 256 + threadIdx.x;
    if (e < EE) atomicAdd(&g_deg[ei[EE + e]], 1);
}

// ---------------- scan phase 1 (+ dinv fused) ----------------
__global__ void k_scan1() {
    __shared__ int wsum[32];
    int tid = threadIdx.x;               // 1024
    int lane = tid & 31, wid = tid >> 5;
    int i = blockIdx.x * 1024 + tid;
    int deg = (i < NN) ? g_deg[i] : 1;
    if (i < NN) g_dinv[i] = rsqrtf((float)deg);
    int v = (i < NN) ? deg - 1 : 0;
    int incl = v;
    #pragma unroll
    for (int o = 1; o < 32; o <<= 1) {
        int t = __shfl_up_sync(0xffffffffu, incl, o);
        if (lane >= o) incl += t;
    }
    if (lane == 31) wsum[wid] = incl;
    __syncthreads();
    if (wid == 0) {
        int s = wsum[lane];
        #pragma unroll
        for (int o = 1; o < 32; o <<= 1) {
            int t = __shfl_up_sync(0xffffffffu, s, o);
            if (lane >= o) s += t;
        }
        wsum[lane] = s;
    }
    __syncthreads();
    int excl = (wid ? wsum[wid - 1] : 0) + incl - v;
    if (i < NN) g_rowptr[i] = excl;      // block-local for now
    if (tid == 1023) g_bsum[blockIdx.x] = wsum[31];   // sole writer
}

__global__ void k_scan2() {
    if (threadIdx.x == 0) {
        int run = 0;
        for (int b = 0; b < SCAN_BLOCKS; b++) {
            g_boff[b] = run;
            run += g_bsum[b];
        }
    }
}

__global__ void k_scan3() {
    int i = blockIdx.x * 256 + threadIdx.x;
    if (i < NN) {
        int r = g_rowptr[i] + g_boff[i >> 10];
        g_rowptr[i] = r;
        g_cursor[i] = r;
    }
    if (i == 0) g_rowptr[NN] = EE;       // sum(deg-1) == E exactly
}

// ---------------- CSR fill ----------------
__global__ void k_fill(const int* __restrict__ ei) {
    int e = blockIdx.x * 256 + threadIdx.x;
    if (e >= EE) return;
    int s = ei[e], d = ei[EE + e];
    int p = atomicAdd(&g_cursor[d], 1);
    g_csr[p] = make_int2(s, __float_as_int(g_dinv[s] * g_dinv[d]));
}

// ---------------- node embedding: node per thread ----------------
__global__ void __launch_bounds__(256) k_embed(const float* __restrict__ x,
                                               const float* __restrict__ W,
                                               const float* __restrict__ b) {
    __shared__ float Ws[16 * 64];
    __shared__ float bs[64];
    int tid = threadIdx.x;
    for (int i = tid; i < 16 * 64; i += 256) Ws[i] = W[i];
    if (tid < 64) bs[tid] = b[tid];
    __syncthreads();
    int n = blockIdx.x * 256 + tid;
    if (n >= NN) return;
    float acc[64];
    #pragma unroll
    for (int h = 0; h < 64; h++) acc[h] = bs[h];
    const float4* x4 = (const float4*)(x + (size_t)n * 16);
    #pragma unroll
    for (int k4 = 0; k4 < 4; k4++) {
        float4 xv = x4[k4];
        #pragma unroll
        for (int kk = 0; kk < 4; kk++) {
            float xk = (&xv.x)[kk];
            const float4* wrow = (const float4*)(Ws + (k4 * 4 + kk) * 64);
            #pragma unroll
            for (int h4 = 0; h4 < 16; h4++) {
                float4 w = wrow[h4];
                float* a = acc + 4 * h4;
                a[0] = fmaf(xk, w.x, a[0]);
                a[1] = fmaf(xk, w.y, a[1]);
                a[2] = fmaf(xk, w.z, a[2]);
                a[3] = fmaf(xk, w.w, a[3]);
            }
        }
    }
    float4* o4 = (float4*)(g_x + (size_t)n * 64);
    #pragma unroll
    for (int h4 = 0; h4 < 16; h4++)
        o4[h4] = make_float4(acc[4*h4], acc[4*h4+1], acc[4*h4+2], acc[4*h4+3]);
}

// ---------------- gather: hw[n] = sum nrm*x[src] + dinv^2*x[n] --------------
__global__ void k_gather() {
    int t = blockIdx.x * 256 + threadIdx.x;
    int node = t >> 5;
    if (node >= NN) return;
    int lane = t & 31;
    const float2* x2 = (const float2*)g_x;
    int beg = g_rowptr[node], end = g_rowptr[node + 1];
    float di = g_dinv[node];
    float2 acc = x2[node * 32 + lane];
    acc.x *= di * di; acc.y *= di * di;
    float2 acc2 = make_float2(0.f, 0.f);
    int i = beg;
    if ((i & 1) && i < end) {            // align to int4 boundary
        int2 a = g_csr[i];
        float2 va = x2[a.x * 32 + lane];
        float na = __int_as_float(a.y);
        acc.x = fmaf(na, va.x, acc.x); acc.y = fmaf(na, va.y, acc.y);
        i++;
    }
    for (; i + 3 < end; i += 4) {        // 4 independent gathers in flight
        int4 c0 = *(const int4*)&g_csr[i];
        int4 c1 = *(const int4*)&g_csr[i + 2];
        float2 v0 = x2[c0.x * 32 + lane];
        float2 v1 = x2[c0.z * 32 + lane];
        float2 v2 = x2[c1.x * 32 + lane];
        float2 v3 = x2[c1.z * 32 + lane];
        float n0 = __int_as_float(c0.y), n1 = __int_as_float(c0.w);
        float n2 = __int_as_float(c1.y), n3 = __int_as_float(c1.w);
        acc.x  = fmaf(n0, v0.x, acc.x);  acc.y  = fmaf(n0, v0.y, acc.y);
        acc2.x = fmaf(n1, v1.x, acc2.x); acc2.y = fmaf(n1, v1.y, acc2.y);
        acc.x  = fmaf(n2, v2.x, acc.x);  acc.y  = fmaf(n2, v2.y, acc.y);
        acc2.x = fmaf(n3, v3.x, acc2.x); acc2.y = fmaf(n3, v3.y, acc2.y);
    }
    for (; i < end; i++) {
        int2 a = g_csr[i];
        float2 va = x2[a.x * 32 + lane];
        float na = __int_as_float(a.y);
        acc.x = fmaf(na, va.x, acc.x); acc.y = fmaf(na, va.y, acc.y);
    }
    acc.x += acc2.x; acc.y += acc2.y;
    ((float2*)g_hw)[node * 32 + lane] = acc;
}

// ------- GEMM + fused BN stats + last-block BN finalize ---------------------
__global__ void __launch_bounds__(256) k_gemm(const float* __restrict__ W,
                                              const float* __restrict__ b,
                                              const float* __restrict__ gamma,
                                              const float* __restrict__ beta) {
    __shared__ float Ws[64 * 64];
    __shared__ float bs[64];
    __shared__ float s_sum[8][64];
    __shared__ float s_sq[8][64];
    __shared__ float sh[128];
    __shared__ int   lastflag;
    int tid = threadIdx.x;               // 256
    int lane = tid & 31, wid = tid >> 5;
    for (int i = tid; i < 64 * 64; i += 256) Ws[i] = W[i];
    if (tid < 64) bs[tid] = b[tid];
    __syncthreads();
    int n = blockIdx.x * 256 + tid;
    bool valid = (n < NN);
    float acc[64];
    #pragma unroll
    for (int h = 0; h < 64; h++) acc[h] = 0.f;
    if (valid) {
        const float4* x4 = (const float4*)(g_hw + (size_t)n * 64);
        for (int k4 = 0; k4 < 16; k4++) {
            float4 xk = x4[k4];
            const float* base = Ws + k4 * 256;
            #pragma unroll
            for (int h4 = 0; h4 < 16; h4++) {
                float4 w0 = ((const float4*)(base      ))[h4];
                float4 w1 = ((const float4*)(base +  64))[h4];
                float4 w2 = ((const float4*)(base + 128))[h4];
                float4 w3 = ((const float4*)(base + 192))[h4];
                float* a = acc + 4 * h4;
                a[0] = fmaf(xk.x, w0.x, fmaf(xk.y, w1.x, fmaf(xk.z, w2.x, fmaf(xk.w, w3.x, a[0]))));
                a[1] = fmaf(xk.x, w0.y, fmaf(xk.y, w1.y, fmaf(xk.z, w2.y, fmaf(xk.w, w3.y, a[1]))));
                a[2] = fmaf(xk.x, w0.z, fmaf(xk.y, w1.z, fmaf(xk.z, w2.z, fmaf(xk.w, w3.z, a[2]))));
                a[3] = fmaf(xk.x, w0.w, fmaf(xk.y, w1.w, fmaf(xk.z, w2.w, fmaf(xk.w, w3.w, a[3]))));
            }
        }
        float4* o4 = (float4*)(g_agg + (size_t)n * 64);
        #pragma unroll
        for (int h4 = 0; h4 < 16; h4++) {
            float4 o;
            o.x = acc[4*h4+0] + bs[4*h4+0];
            o.y = acc[4*h4+1] + bs[4*h4+1];
            o.z = acc[4*h4+2] + bs[4*h4+2];
            o.w = acc[4*h4+3] + bs[4*h4+3];
            o4[h4] = o;
        }
    }
    // per-feature warp reduction of agg value (= acc + bias) and its square
    #pragma unroll
    for (int h = 0; h < 64; h++) {
        float v = valid ? acc[h] + bs[h] : 0.f;
        float q = v * v;
        #pragma unroll
        for (int o = 16; o; o >>= 1) {
            v += __shfl_down_sync(0xffffffffu, v, o);
            q += __shfl_down_sync(0xffffffffu, q, o);
        }
        if (lane == 0) { s_sum[wid][h] = v; s_sq[wid][h] = q; }
    }
    __syncthreads();
    if (tid < 64) {
        float s = 0.f;
        #pragma unroll
        for (int w = 0; w < 8; w++) s += s_sum[w][tid];
        g_part[blockIdx.x * 128 + tid] = s;
    } else if (tid < 128) {
        int f = tid - 64;
        float q = 0.f;
        #pragma unroll
        for (int w = 0; w < 8; w++) q += s_sq[w][f];
        g_part[blockIdx.x * 128 + 64 + f] = q;
    }
    __threadfence();
    if (tid == 0) lastflag = (atomicAdd(&g_ticket, 1u) == (unsigned)(gridDim.x - 1));
    __syncthreads();
    if (lastflag) {
        if (tid < 128) {
            float s = 0.f;
            for (int i = 0; i < GB; i++) s += g_part[i * 128 + tid];
            sh[tid] = s;
        }
        __syncthreads();
        if (tid < 64) {
            float mean = sh[tid] * (1.0f / NN);
            float var  = sh[64 + tid] * (1.0f / NN) - mean * mean;
            float sc   = gamma[tid] * rsqrtf(var + BN_EPS);
            g_scale[tid] = sc;
            g_shift[tid] = beta[tid] - mean * sc;
        }
        if (tid == 0) g_ticket = 0;      // reset for next layer / replay
    }
}

// ---------------- BN apply + ReLU + residual ----------------
__global__ void k_apply() {
    int id = blockIdx.x * 256 + threadIdx.x;   // over N*16 float4s
    if (id >= NN * 16) return;
    int c = id & 15;
    float4 a = reinterpret_cast<const float4*>(g_agg)[id];
    float4 sc = reinterpret_cast<const float4*>(g_scale)[c];
    float4 sf = reinterpret_cast<const float4*>(g_shift)[c];
    float4 xv = reinterpret_cast<const float4*>(g_x)[id];
    xv.x += fmaxf(fmaf(a.x, sc.x, sf.x), 0.f);
    xv.y += fmaxf(fmaf(a.y, sc.y, sf.y), 0.f);
    xv.z += fmaxf(fmaf(a.z, sc.z, sf.z), 0.f);
    xv.w += fmaxf(fmaf(a.w, sc.w, sf.w), 0.f);
    reinterpret_cast<float4*>(g_x)[id] = xv;
}

// ------- last layer: BN apply + ReLU + residual + edge-head precompute -----
__global__ void __launch_bounds__(256) k_apply_head(const float* __restrict__ fcW) {
    __shared__ float sc[64], sf[64], Wh[256];
    int tid = threadIdx.x;
    if (tid < 64)  sc[tid] = g_scale[tid];
    else if (tid < 128) sf[tid - 64] = g_shift[tid - 64];
    if (tid < 256) { if (tid < 256) { } }
    for (int i = tid; i < 256; i += 256) Wh[i] = fcW[i];
    __syncthreads();
    int n = blockIdx.x * 256 + tid;
    if (n >= NN) return;
    const float4* a4 = (const float4*)(g_agg + (size_t)n * 64);
    const float4* x4 = (const float4*)(g_x   + (size_t)n * 64);
    float a0 = 0.f, a1 = 0.f, b0 = 0.f, b1 = 0.f;
    #pragma unroll
    for (int h4 = 0; h4 < 16; h4++) {
        float4 a = a4[h4];
        float4 xv = x4[h4];
        #pragma unroll
        for (int kk = 0; kk < 4; kk++) {
            int h = h4 * 4 + kk;
            float val = (&xv.x)[kk] +
                        fmaxf(fmaf((&a.x)[kk], sc[h], sf[h]), 0.f);
            a0 = fmaf(val, Wh[h * 2],            a0);
            a1 = fmaf(val, Wh[h * 2 + 1],        a1);
            b0 = fmaf(val, Wh[(64 + h) * 2],     b0);
            b1 = fmaf(val, Wh[(64 + h) * 2 + 1], b1);
        }
    }
    g_head[n] = make_float4(a0, a1, b0, b1);   // x not stored: nothing reads it
}

// ---------------- edge head: out[e] = a[src] + b[dst] + fcb -----------------
__global__ void k_final(const int* __restrict__ eio,
                        const float* __restrict__ fcb,
                        float* __restrict__ out) {
    int e = blockIdx.x * 256 + threadIdx.x;
    if (e >= EOUT) return;
    int s = eio[e];
    int d = eio[EOUT + e];
    float4 hs = g_head[s];
    float4 hd = g_head[d];
    float2 o;
    o.x = hs.x + hd.z + fcb[0];
    o.y = hs.y + hd.w + fcb[1];
    ((float2*)out)[e] = o;
}

// ---------------- launch ----------------
extern "C" void kernel_launch(void* const* d_in, const int* in_sizes, int n_in,
                              void* d_out, int out_size) {
    const float* x    = (const float*)d_in[0];
    const int*   ei   = (const int*)d_in[1];
    const int*   eio  = (const int*)d_in[2];
    const float* Wemb = (const float*)d_in[3];
    const float* bemb = (const float*)d_in[4];
    const float* convW= (const float*)d_in[5];
    const float* convb= (const float*)d_in[6];
    const float* gam  = (const float*)d_in[7];
    const float* bet  = (const float*)d_in[8];
    const float* fcW  = (const float*)d_in[9];
    const float* fcb  = (const float*)d_in[10];
    float*       out  = (float*)d_out;

    k_deg_init<<<(NN + 255) / 256, 256>>>();
    k_deg_count<<<(EE + 255) / 256, 256>>>(ei);
    k_scan1<<<SCAN_BLOCKS, 1024>>>();
    k_scan2<<<1, 32>>>();
    k_scan3<<<(NN + 255) / 256, 256>>>();
    k_fill<<<(EE + 255) / 256, 256>>>(ei);
    k_embed<<<GB, 256>>>(x, Wemb, bemb);

    for (int l = 0; l < 6; l++) {
        k_gather<<<(NN * 32 + 255) / 256, 256>>>();
        k_gemm<<<GB, 256>>>(convW + l * 64 * 64, convb + l * 64,
                            gam + l * 64, bet + l * 64);
        if (l < 5) k_apply<<<(NN * 16 + 255) / 256, 256>>>();
        else       k_apply_head<<<GB, 256>>>(fcW);
    }

    k_final<<<(EOUT + 255) / 256, 256>>>(eio, fcb, out);
}

// round 7
// speedup vs baseline: 1.1023x; 1.1023x over previous
#include <cuda_runtime.h>
#include <cuda_bf16.h>

#define NN   100000
#define EE   1600000
#define EOUT 400000
#define HIDD 64
#define GB   ((NN + 255) / 256)
#define STATS_BLOCKS 128
#define SCAN_BLOCKS  ((NN + 1023) / 1024)
#define BN_EPS 1e-5f

// ---------------- scratch (device globals; no allocation) ----------------
__device__ float g_dinv[NN];
__device__ int   g_deg[NN];
__device__ int   g_rowptr[NN + 1];
__device__ int   g_cursor[NN];
__device__ int   g_bsum[SCAN_BLOCKS];
__device__ int   g_boff[SCAN_BLOCKS];
__device__ int2  g_csr[EE];          // (src, norm-bits)
__device__ float g_x  [NN * HIDD];   // x_embed
__device__ float g_hw [NN * HIDD];   // aggregated x (pre-GEMM)
__device__ float g_agg[NN * HIDD];   // conv output
__device__ float g_part[STATS_BLOCKS * 128];
__device__ float g_scale[HIDD];
__device__ float g_shift[HIDD];
__device__ float4 g_head[NN];        // (a0,a1,b0,b1) edge-head halves

// ---------------- degree ----------------
__global__ void k_deg_init() {
    int i = blockIdx.x * 256 + threadIdx.x;
    if (i < NN) g_deg[i] = 1;            // self loop
}

__global__ void k_deg_count(const int* __restrict__ ei) {
    int e = blockIdx.x * 256 + threadIdx.x;
    if (e < EE) atomicAdd(&g_deg[ei[EE + e]], 1);
}

// ---------------- scan phase 1 (+ dinv fused) ----------------
__global__ void k_scan1() {
    __shared__ int wsum[32];
    int tid = threadIdx.x;               // 1024
    int lane = tid & 31, wid = tid >> 5;
    int i = blockIdx.x * 1024 + tid;
    int deg = (i < NN) ? g_deg[i] : 1;
    if (i < NN) g_dinv[i] = rsqrtf((float)deg);
    int v = (i < NN) ? deg - 1 : 0;
    int incl = v;
    #pragma unroll
    for (int o = 1; o < 32; o <<= 1) {
        int t = __shfl_up_sync(0xffffffffu, incl, o);
        if (lane >= o) incl += t;
    }
    if (lane == 31) wsum[wid] = incl;
    __syncthreads();
    if (wid == 0) {
        int s = wsum[lane];
        #pragma unroll
        for (int o = 1; o < 32; o <<= 1) {
            int t = __shfl_up_sync(0xffffffffu, s, o);
            if (lane >= o) s += t;
        }
        wsum[lane] = s;
    }
    __syncthreads();
    int excl = (wid ? wsum[wid - 1] : 0) + incl - v;
    if (i < NN) g_rowptr[i] = excl;      // block-local for now
    if (tid == 1023) g_bsum[blockIdx.x] = wsum[31];   // sole writer
}

// ---------------- scan phase 2: parallel scan of 98 block sums ----------
__global__ void k_scan2() {
    __shared__ int sh[128];
    int t = threadIdx.x;                 // 128
    sh[t] = (t < SCAN_BLOCKS) ? g_bsum[t] : 0;
    __syncthreads();
    #pragma unroll
    for (int o = 1; o < 128; o <<= 1) {
        int v = (t >= o) ? sh[t - o] : 0;
        __syncthreads();
        sh[t] += v;
        __syncthreads();
    }
    if (t < SCAN_BLOCKS) g_boff[t] = sh[t] - g_bsum[t];  // exclusive
}

__global__ void k_scan3() {
    int i = blockIdx.x * 256 + threadIdx.x;
    if (i < NN) {
        int r = g_rowptr[i] + g_boff[i >> 10];
        g_rowptr[i] = r;
        g_cursor[i] = r;
    }
    if (i == 0) g_rowptr[NN] = EE;       // sum(deg-1) == E exactly
}

// ---------------- CSR fill ----------------
__global__ void k_fill(const int* __restrict__ ei) {
    int e = blockIdx.x * 256 + threadIdx.x;
    if (e >= EE) return;
    int s = ei[e], d = ei[EE + e];
    int p = atomicAdd(&g_cursor[d], 1);
    g_csr[p] = make_int2(s, __float_as_int(g_dinv[s] * g_dinv[d]));
}

// ---------------- node embedding: node per thread ----------------
__global__ void __launch_bounds__(256) k_embed(const float* __restrict__ x,
                                               const float* __restrict__ W,
                                               const float* __restrict__ b) {
    __shared__ float Ws[16 * 64];
    __shared__ float bs[64];
    int tid = threadIdx.x;
    for (int i = tid; i < 16 * 64; i += 256) Ws[i] = W[i];
    if (tid < 64) bs[tid] = b[tid];
    __syncthreads();
    int n = blockIdx.x * 256 + tid;
    if (n >= NN) return;
    float acc[64];
    #pragma unroll
    for (int h = 0; h < 64; h++) acc[h] = bs[h];
    const float4* x4 = (const float4*)(x + (size_t)n * 16);
    #pragma unroll
    for (int k4 = 0; k4 < 4; k4++) {
        float4 xv = x4[k4];
        #pragma unroll
        for (int kk = 0; kk < 4; kk++) {
            float xk = (&xv.x)[kk];
            const float4* wrow = (const float4*)(Ws + (k4 * 4 + kk) * 64);
            #pragma unroll
            for (int h4 = 0; h4 < 16; h4++) {
                float4 w = wrow[h4];
                float* a = acc + 4 * h4;
                a[0] = fmaf(xk, w.x, a[0]);
                a[1] = fmaf(xk, w.y, a[1]);
                a[2] = fmaf(xk, w.z, a[2]);
                a[3] = fmaf(xk, w.w, a[3]);
            }
        }
    }
    float4* o4 = (float4*)(g_x + (size_t)n * 64);
    #pragma unroll
    for (int h4 = 0; h4 < 16; h4++)
        o4[h4] = make_float4(acc[4*h4], acc[4*h4+1], acc[4*h4+2], acc[4*h4+3]);
}

// ---------------- gather: hw[n] = sum nrm*x[src] + dinv^2*x[n] --------------
__global__ void k_gather() {
    int t = blockIdx.x * 256 + threadIdx.x;
    int node = t >> 5;
    if (node >= NN) return;
    int lane = t & 31;
    const float2* x2 = (const float2*)g_x;
    int beg = g_rowptr[node], end = g_rowptr[node + 1];
    float di = g_dinv[node];
    float2 acc = x2[node * 32 + lane];
    acc.x *= di * di; acc.y *= di * di;
    float2 acc2 = make_float2(0.f, 0.f);
    int i = beg;
    if ((i & 1) && i < end) {            // align to int4 boundary
        int2 a = g_csr[i];
        float2 va = x2[a.x * 32 + lane];
        float na = __int_as_float(a.y);
        acc.x = fmaf(na, va.x, acc.x); acc.y = fmaf(na, va.y, acc.y);
        i++;
    }
    for (; i + 3 < end; i += 4) {        // 4 independent gathers in flight
        int4 c0 = *(const int4*)&g_csr[i];
        int4 c1 = *(const int4*)&g_csr[i + 2];
        float2 v0 = x2[c0.x * 32 + lane];
        float2 v1 = x2[c0.z * 32 + lane];
        float2 v2 = x2[c1.x * 32 + lane];
        float2 v3 = x2[c1.z * 32 + lane];
        float n0 = __int_as_float(c0.y), n1 = __int_as_float(c0.w);
        float n2 = __int_as_float(c1.y), n3 = __int_as_float(c1.w);
        acc.x  = fmaf(n0, v0.x, acc.x);  acc.y  = fmaf(n0, v0.y, acc.y);
        acc2.x = fmaf(n1, v1.x, acc2.x); acc2.y = fmaf(n1, v1.y, acc2.y);
        acc.x  = fmaf(n2, v2.x, acc.x);  acc.y  = fmaf(n2, v2.y, acc.y);
        acc2.x = fmaf(n3, v3.x, acc2.x); acc2.y = fmaf(n3, v3.y, acc2.y);
    }
    for (; i < end; i++) {
        int2 a = g_csr[i];
        float2 va = x2[a.x * 32 + lane];
        float na = __int_as_float(a.y);
        acc.x = fmaf(na, va.x, acc.x); acc.y = fmaf(na, va.y, acc.y);
    }
    acc.x += acc2.x; acc.y += acc2.y;
    ((float2*)g_hw)[node * 32 + lane] = acc;
}

// ---------------- GEMM: agg = hw @ W + b (node per thread) ------------------
__global__ void __launch_bounds__(256) k_gemm(const float* __restrict__ W,
                                              const float* __restrict__ b) {
    __shared__ float Ws[64 * 64];
    __shared__ float bs[64];
    int tid = threadIdx.x;               // 256
    for (int i = tid; i < 64 * 64; i += 256) Ws[i] = W[i];
    if (tid < 64) bs[tid] = b[tid];
    __syncthreads();
    int n = blockIdx.x * 256 + tid;
    if (n >= NN) return;
    float acc[64];
    #pragma unroll
    for (int h = 0; h < 64; h++) acc[h] = 0.f;
    const float4* x4 = (const float4*)(g_hw + (size_t)n * 64);
    for (int k4 = 0; k4 < 16; k4++) {
        float4 xk = x4[k4];
        const float* base = Ws + k4 * 256;
        #pragma unroll
        for (int h4 = 0; h4 < 16; h4++) {
            float4 w0 = ((const float4*)(base      ))[h4];
            float4 w1 = ((const float4*)(base +  64))[h4];
            float4 w2 = ((const float4*)(base + 128))[h4];
            float4 w3 = ((const float4*)(base + 192))[h4];
            float* a = acc + 4 * h4;
            a[0] = fmaf(xk.x, w0.x, fmaf(xk.y, w1.x, fmaf(xk.z, w2.x, fmaf(xk.w, w3.x, a[0]))));
            a[1] = fmaf(xk.x, w0.y, fmaf(xk.y, w1.y, fmaf(xk.z, w2.y, fmaf(xk.w, w3.y, a[1]))));
            a[2] = fmaf(xk.x, w0.z, fmaf(xk.y, w1.z, fmaf(xk.z, w2.z, fmaf(xk.w, w3.z, a[2]))));
            a[3] = fmaf(xk.x, w0.w, fmaf(xk.y, w1.w, fmaf(xk.z, w2.w, fmaf(xk.w, w3.w, a[3]))));
        }
    }
    float4* o4 = (float4*)(g_agg + (size_t)n * 64);
    #pragma unroll
    for (int h4 = 0; h4 < 16; h4++) {
        float4 o;
        o.x = acc[4 * h4 + 0] + bs[4 * h4 + 0];
        o.y = acc[4 * h4 + 1] + bs[4 * h4 + 1];
        o.z = acc[4 * h4 + 2] + bs[4 * h4 + 2];
        o.w = acc[4 * h4 + 3] + bs[4 * h4 + 3];
        o4[h4] = o;
    }
}

// ---------------- BN stats ----------------
__global__ void k_stats() {
    __shared__ float ss[256], sq[256];
    int t = threadIdx.x;                 // 256
    int f = t & 63, g = t >> 6;
    float s = 0.f, q = 0.f;
    for (int n = blockIdx.x * 4 + g; n < NN; n += STATS_BLOCKS * 4) {
        float v = g_agg[n * 64 + f];
        s += v; q = fmaf(v, v, q);
    }
    ss[t] = s; sq[t] = q;
    __syncthreads();
    if (g == 0) {
        s = ss[f] + ss[64 + f] + ss[128 + f] + ss[192 + f];
        q = sq[f] + sq[64 + f] + sq[128 + f] + sq[192 + f];
        g_part[blockIdx.x * 128 + f]      = s;
        g_part[blockIdx.x * 128 + 64 + f] = q;
    }
}

__global__ void k_bnfin(const float* __restrict__ gamma,
                        const float* __restrict__ beta) {
    __shared__ float sh[128];
    int t = threadIdx.x;                 // 128
    float s = 0.f;
    #pragma unroll 4
    for (int i = 0; i < STATS_BLOCKS; i++) s += g_part[i * 128 + t];
    sh[t] = s;
    __syncthreads();
    if (t < 64) {
        float mean = sh[t] * (1.0f / NN);
        float var  = sh[64 + t] * (1.0f / NN) - mean * mean;
        float sc   = gamma[t] * rsqrtf(var + BN_EPS);
        g_scale[t] = sc;
        g_shift[t] = beta[t] - mean * sc;
    }
}

// ---------------- BN apply + ReLU + residual ----------------
__global__ void k_apply() {
    int id = blockIdx.x * 256 + threadIdx.x;   // over N*16 float4s
    if (id >= NN * 16) return;
    int c = id & 15;
    float4 a = reinterpret_cast<const float4*>(g_agg)[id];
    float4 sc = reinterpret_cast<const float4*>(g_scale)[c];
    float4 sf = reinterpret_cast<const float4*>(g_shift)[c];
    float4 xv = reinterpret_cast<const float4*>(g_x)[id];
    xv.x += fmaxf(fmaf(a.x, sc.x, sf.x), 0.f);
    xv.y += fmaxf(fmaf(a.y, sc.y, sf.y), 0.f);
    xv.z += fmaxf(fmaf(a.z, sc.z, sf.z), 0.f);
    xv.w += fmaxf(fmaf(a.w, sc.w, sf.w), 0.f);
    reinterpret_cast<float4*>(g_x)[id] = xv;
}

// ------- last layer: BN apply + ReLU + residual + edge-head precompute -----
__global__ void __launch_bounds__(256) k_apply_head(const float* __restrict__ fcW) {
    __shared__ float sc[64], sf[64], Wh[256];
    int tid = threadIdx.x;
    if (tid < 64)  sc[tid] = g_scale[tid];
    else if (tid < 128) sf[tid - 64] = g_shift[tid - 64];
    for (int i = tid; i < 256; i += 256) Wh[i] = fcW[i];
    __syncthreads();
    int n = blockIdx.x * 256 + tid;
    if (n >= NN) return;
    const float4* a4 = (const float4*)(g_agg + (size_t)n * 64);
    const float4* x4 = (const float4*)(g_x   + (size_t)n * 64);
    float a0 = 0.f, a1 = 0.f, b0 = 0.f, b1 = 0.f;
    #pragma unroll
    for (int h4 = 0; h4 < 16; h4++) {
        float4 a = a4[h4];
        float4 xv = x4[h4];
        #pragma unroll
        for (int kk = 0; kk < 4; kk++) {
            int h = h4 * 4 + kk;
            float val = (&xv.x)[kk] +
                        fmaxf(fmaf((&a.x)[kk], sc[h], sf[h]), 0.f);
            a0 = fmaf(val, Wh[h * 2],            a0);
            a1 = fmaf(val, Wh[h * 2 + 1],        a1);
            b0 = fmaf(val, Wh[(64 + h) * 2],     b0);
            b1 = fmaf(val, Wh[(64 + h) * 2 + 1], b1);
        }
    }
    g_head[n] = make_float4(a0, a1, b0, b1);   // x not stored: nothing reads it
}

// ---------------- edge head: out[e] = a[src] + b[dst] + fcb -----------------
__global__ void k_final(const int* __restrict__ eio,
                        const float* __restrict__ fcb,
                        float* __restrict__ out) {
    int e = blockIdx.x * 256 + threadIdx.x;
    if (e >= EOUT) return;
    int s = eio[e];
    int d = eio[EOUT + e];
    float4 hs = g_head[s];
    float4 hd = g_head[d];
    float2 o;
    o.x = hs.x + hd.z + fcb[0];
    o.y = hs.y + hd.w + fcb[1];
    ((float2*)out)[e] = o;
}

// ---------------- launch ----------------
extern "C" void kernel_launch(void* const* d_in, const int* in_sizes, int n_in,
                              void* d_out, int out_size) {
    const float* x    = (const float*)d_in[0];
    const int*   ei   = (const int*)d_in[1];
    const int*   eio  = (const int*)d_in[2];
    const float* Wemb = (const float*)d_in[3];
    const float* bemb = (const float*)d_in[4];
    const float* convW= (const float*)d_in[5];
    const float* convb= (const float*)d_in[6];
    const float* gam  = (const float*)d_in[7];
    const float* bet  = (const float*)d_in[8];
    const float* fcW  = (const float*)d_in[9];
    const float* fcb  = (const float*)d_in[10];
    float*       out  = (float*)d_out;

    k_deg_init<<<(NN + 255) / 256, 256>>>();
    k_deg_count<<<(EE + 255) / 256, 256>>>(ei);
    k_scan1<<<SCAN_BLOCKS, 1024>>>();
    k_scan2<<<1, 128>>>();
    k_scan3<<<(NN + 255) / 256, 256>>>();
    k_fill<<<(EE + 255) / 256, 256>>>(ei);
    k_embed<<<GB, 256>>>(x, Wemb, bemb);

    for (int l = 0; l < 6; l++) {
        k_gather<<<(NN * 32 + 255) / 256, 256>>>();
        k_gemm<<<GB, 256>>>(convW + l * 64 * 64, convb + l * 64);
        k_stats<<<STATS_BLOCKS, 256>>>();
        k_bnfin<<<1, 128>>>(gam + l * 64, bet + l * 64);
        if (l < 5) k_apply<<<(NN * 16 + 255) / 256, 256>>>();
        else       k_apply_head<<<GB, 256>>>(fcW);
    }

    k_final<<<(EOUT + 255) / 256, 256>>>(eio, fcb, out);
}